// round 11
// baseline (speedup 1.0000x reference)
#include <cuda_runtime.h>
#include <math.h>

// Problem constants
#define TAU   0.07f
#define BB    8
#define CC    128
#define HH    512
#define WW    512
#define HWSZ  (HH*WW)
#define KK    64
#define NNEG  7
#define PP    4096
#define NQ    (BB*KK)          // 512
#define CPAD  68               // pool smem row stride (words)
#define NPB   64               // pool blocks of 64 rows

// Device scratch (allocation-free)
__device__ float4 g_q[NQ * 32];          // RAW gathered queries [NQ][C]
__device__ float  g_pinv[PP];            // pool inverse norms
__device__ float  g_pmax_val[NQ * NPB];  // per (query,pool-block) max cos*|q|
__device__ float  g_loss[NQ];
__device__ volatile int g_gcnt[8];       // GEMM arrivals per query-block
__device__ int    g_ticket;

__device__ __forceinline__ void ffma2(unsigned long long& d,
                                      unsigned long long a,
                                      unsigned long long b) {
    asm("fma.rn.f32x2 %0, %1, %2, %0;" : "+l"(d) : "l"(a), "l"(b));
}

// ---------------------------------------------------------------------------
// Kernel 1: gather (TLB-friendly: warp = one (b,c) page, lanes = k)
//           + pool inverse norms + flag/ticket reset. 256 blocks x 256 thr.
// ---------------------------------------------------------------------------
__global__ void __launch_bounds__(256)
prep_kernel(const float* __restrict__ qf,
            const float* __restrict__ pool,
            const int*   __restrict__ qidx) {
    int t = threadIdx.x, bid = blockIdx.x;
    int w = t >> 5, lane = t & 31;
    if (bid == 0 && t < 8) g_gcnt[t] = 0;
    if (bid == 0 && t == 8) g_ticket = 0;

    int e = bid * 256 + t;
    int k = e & 63;
    int c = (e >> 6) & 127;
    int b = e >> 13;
    int idx = qidx[b * KK + k];
    float v = qf[(long)(b * CC + c) * HWSZ + idx];

    #pragma unroll
    for (int j = 0; j < 2; j++) {
        int r = bid * 16 + w * 2 + j;
        float4 u = ((const float4*)pool)[r * 32 + lane];
        float ss = u.x*u.x + u.y*u.y + u.z*u.z + u.w*u.w;
        #pragma unroll
        for (int o = 16; o > 0; o >>= 1) ss += __shfl_xor_sync(0xFFFFFFFFu, ss, o);
        if (lane == 0) g_pinv[r] = 1.0f / fmaxf(sqrtf(ss), 1e-12f);
    }

    ((float*)g_q)[(b * KK + k) * CC + c] = v;
}

// ---------------------------------------------------------------------------
// Kernel 2: GEMM + fused finalize. grid = 512 (bid = qblk*64 + pblk), 128 thr.
// GEMM: tile 64q x 64p, micro 8q x 4p, f32x2. Mainloop hoists ALL 12 LDS.128
// per c4 step before the 64 FFMA2s (short-scoreboard latency hiding).
// Blocks with pblk < 16 then finalize (warp = one query); ticket-elected
// last finalize block does the deterministic mean.
// ---------------------------------------------------------------------------
__global__ void __launch_bounds__(128, 4)
gemm_fin_kernel(const float* __restrict__ pool,
                const float* __restrict__ negs,
                float* __restrict__ out) {
    __shared__ float q_s[64 * 64];      // 16 KB
    __shared__ float p_s[64 * CPAD];    // 17.4 KB
    __shared__ int   s_last;

    int t = threadIdx.x, bid = blockIdx.x;
    int tx = t & 15, ty = t >> 4;
    int qblk = bid >> 6, pblk = bid & 63;
    int qbase = qblk * 64, pbase = pblk * 64;
    int w = t >> 5, lane = t & 31;

    unsigned long long acc2[8][4];
    #pragma unroll
    for (int i = 0; i < 8; i++)
        #pragma unroll
        for (int j = 0; j < 4; j++) acc2[i][j] = 0ULL;

    const float* qrow = q_s + ty * 8 * 64;      // this thread's 8 query rows
    const float* prow = p_s + tx * CPAD;        // this thread's 4 pool rows

    for (int kc = 0; kc < 2; kc++) {
        if (kc) __syncthreads();
        #pragma unroll
        for (int it = 0; it < 8; it++) {
            int idx = t + it * 128;
            int r = idx >> 4, c4 = idx & 15;
            float4 v = g_q[(qbase + r) * 32 + kc * 16 + c4];
            *(float4*)(q_s + r * 64 + c4 * 4) = v;
            float4 u = ((const float4*)pool)[(pbase + r) * 32 + kc * 16 + c4];
            float s = g_pinv[pbase + r];
            u.x *= s; u.y *= s; u.z *= s; u.w *= s;
            *(float4*)(p_s + r * CPAD + c4 * 4) = u;
        }
        __syncthreads();

        #pragma unroll
        for (int c4 = 0; c4 < 16; c4++) {
            union F4 { float4 f; unsigned long long u[2]; };
            // ---- hoist ALL loads for this c4 step (12 x LDS.128) ----
            F4 pv[4], qv[8];
            #pragma unroll
            for (int pj = 0; pj < 4; pj++)
                pv[pj].f = *(const float4*)(prow + 16 * pj * CPAD + c4 * 4);
            #pragma unroll
            for (int qi = 0; qi < 8; qi++)
                qv[qi].f = *(const float4*)(qrow + qi * 64 + c4 * 4);
            // ---- 64 dependent FFMA2s, loads already in flight ----
            #pragma unroll
            for (int qi = 0; qi < 8; qi++)
                #pragma unroll
                for (int pj = 0; pj < 4; pj++) {
                    ffma2(acc2[qi][pj], qv[qi].u[0], pv[pj].u[0]);
                    ffma2(acc2[qi][pj], qv[qi].u[1], pv[pj].u[1]);
                }
        }
    }

    // epilogue: per-thread max over 4 p cols, 16-lane max reduce, store
    float bv[8];
    #pragma unroll
    for (int qi = 0; qi < 8; qi++) {
        float2 d0 = *(float2*)&acc2[qi][0];
        float2 d1 = *(float2*)&acc2[qi][1];
        float2 d2 = *(float2*)&acc2[qi][2];
        float2 d3 = *(float2*)&acc2[qi][3];
        bv[qi] = fmaxf(fmaxf(d0.x + d0.y, d1.x + d1.y),
                       fmaxf(d2.x + d2.y, d3.x + d3.y));
    }
    #pragma unroll
    for (int o = 8; o > 0; o >>= 1) {
        #pragma unroll
        for (int qi = 0; qi < 8; qi++)
            bv[qi] = fmaxf(bv[qi], __shfl_xor_sync(0xFFFFFFFFu, bv[qi], o));
    }
    if (tx == 0) {
        #pragma unroll
        for (int qi = 0; qi < 8; qi++)
            g_pmax_val[(qbase + ty * 8 + qi) * NPB + pblk] = bv[qi];
    }
    __syncthreads();
    if (t == 0) {
        __threadfence();
        atomicAdd((int*)&g_gcnt[qblk], 1);
    }

    if (pblk >= 16) return;   // non-finalize blocks exit, freeing SM slots

    // ---- fused finalize: warp = one query ----
    if (t == 0) {
        while (g_gcnt[qblk] < 64) { __nanosleep(32); }
        __threadfence();
    }
    __syncthreads();

    int q = qbase + pblk * 4 + w;
    int b = q >> 6, k = q & 63;

    // hoist all loads: query vec, 2 pmax partials, 7 negative vecs
    float4 qv = g_q[q * 32 + lane];
    float pm0 = g_pmax_val[q * NPB + lane];
    float pm1 = g_pmax_val[q * NPB + 32 + lane];
    float4 nv[NNEG];
    const float* nbase = negs + ((long)(b * KK + k)) * NNEG * CC;
    #pragma unroll
    for (int n = 0; n < NNEG; n++)
        nv[n] = ((const float4*)(nbase + n * CC))[lane];

    float qss = qv.x*qv.x + qv.y*qv.y + qv.z*qv.z + qv.w*qv.w;
    float v1 = fmaxf(pm0, pm1);
    float ss[NNEG], dt[NNEG];
    #pragma unroll
    for (int n = 0; n < NNEG; n++) {
        ss[n] = nv[n].x*nv[n].x + nv[n].y*nv[n].y + nv[n].z*nv[n].z + nv[n].w*nv[n].w;
        dt[n] = nv[n].x*qv.x + nv[n].y*qv.y + nv[n].z*qv.z + nv[n].w*qv.w;
    }
    #pragma unroll
    for (int o = 16; o > 0; o >>= 1) {
        qss += __shfl_xor_sync(0xFFFFFFFFu, qss, o);
        v1 = fmaxf(v1, __shfl_xor_sync(0xFFFFFFFFu, v1, o));
        #pragma unroll
        for (int n = 0; n < NNEG; n++) {
            ss[n] += __shfl_xor_sync(0xFFFFFFFFu, ss[n], o);
            dt[n] += __shfl_xor_sync(0xFFFFFFFFu, dt[n], o);
        }
    }
    if (lane == 0) {
        float invq = 1.0f / fmaxf(sqrtf(qss), 1e-12f);
        float l0 = v1 * invq / TAU;
        float m = l0;
        float ln[NNEG];
        #pragma unroll
        for (int n = 0; n < NNEG; n++) {
            ln[n] = (dt[n] * invq / fmaxf(sqrtf(ss[n]), 1e-12f)) / TAU;
            m = fmaxf(m, ln[n]);
        }
        float sum = expf(l0 - m);
        #pragma unroll
        for (int n = 0; n < NNEG; n++) sum += expf(ln[n] - m);
        g_loss[q] = m + logf(sum) - l0;
    }
    __syncthreads();

    if (t == 0) {
        __threadfence();
        int tk = atomicAdd(&g_ticket, 1);
        s_last = (tk == 127) ? 1 : 0;
    }
    __syncthreads();

    if (s_last) {
        __shared__ float red[128];
        red[t] = g_loss[t] + g_loss[t + 128] + g_loss[t + 256] + g_loss[t + 384];
        __syncthreads();
        #pragma unroll
        for (int s = 64; s >= 1; s >>= 1) {
            if (t < s) red[t] += red[t + s];
            __syncthreads();
        }
        if (t == 0) out[0] = red[0] / (float)NQ;
    }
}

extern "C" void kernel_launch(void* const* d_in, const int* in_sizes, int n_in,
                              void* d_out, int out_size) {
    const float* query_feat = (const float*)d_in[0];
    const float* pos_pool   = (const float*)d_in[1];
    const float* neg_protos = (const float*)d_in[2];
    const int*   query_idx  = (const int*)d_in[3];
    float* out = (float*)d_out;

    prep_kernel<<<256, 256>>>(query_feat, pos_pool, query_idx);
    gemm_fin_kernel<<<512, 128>>>(pos_pool, neg_protos, out);
}

// round 12
// speedup vs baseline: 1.3477x; 1.3477x over previous
#include <cuda_runtime.h>
#include <cuda_bf16.h>
#include <math.h>
#include <cstdint>

// Problem constants
#define TAU   0.07f
#define BB    8
#define CC    128
#define HH    512
#define WW    512
#define HWSZ  (HH*WW)
#define KK    64
#define NNEG  7
#define PP    4096
#define NQ    (BB*KK)          // 512
#define SROW  144              // smem row stride in bytes (72 bf16 = 64 + 8 pad)

// Device scratch (allocation-free)
__device__ float4 g_q[NQ * 32];        // RAW gathered queries fp32 [NQ][C]
__device__ uint4  g_q_hi[NQ * 16];     // queries bf16 hi [NQ][C]
__device__ uint4  g_q_lo[NQ * 16];     // queries bf16 lo residual
__device__ uint4  g_p_hi[PP * 16];     // NORMALIZED pool bf16 hi [P][C]
__device__ uint4  g_p_lo[PP * 16];     // normalized pool bf16 lo residual
__device__ float  g_pmax_val[NQ * 128];// per (query, pcol-block) max cos*|q|
__device__ float  g_loss_blk[128];
__device__ int    g_ticket;

#define MMA_BF16(D, A0, A1, A2, A3, B0, B1)                                   \
    asm volatile(                                                             \
        "mma.sync.aligned.m16n8k16.row.col.f32.bf16.bf16.f32 "                \
        "{%0,%1,%2,%3}, {%4,%5,%6,%7}, {%8,%9}, {%0,%1,%2,%3};"               \
        : "+f"(D[0]), "+f"(D[1]), "+f"(D[2]), "+f"(D[3])                      \
        : "r"(A0), "r"(A1), "r"(A2), "r"(A3), "r"(B0), "r"(B1))

// ---------------------------------------------------------------------------
// Kernel 1: gather queries (TLB-friendly: warp = one (b,c) page, lanes = k),
// write fp32 + bf16 hi/lo; normalize pool rows and write bf16 hi/lo;
// reset ticket. 256 blocks x 256 threads.
// ---------------------------------------------------------------------------
__global__ void __launch_bounds__(256)
prep_kernel(const float* __restrict__ qf,
            const float* __restrict__ pool,
            const int*   __restrict__ qidx) {
    int t = threadIdx.x, bid = blockIdx.x;
    int w = t >> 5, lane = t & 31;
    if (bid == 0 && t == 0) g_ticket = 0;

    // scattered query gather
    int e = bid * 256 + t;
    int k = e & 63;
    int c = (e >> 6) & 127;
    int b = e >> 13;
    int idx = qidx[b * KK + k];
    float v = qf[(long)(b * CC + c) * HWSZ + idx];

    // pool rows: warp w handles rows bid*16 + w*2 + {0,1}
    #pragma unroll
    for (int j = 0; j < 2; j++) {
        int r = bid * 16 + w * 2 + j;
        float4 u = ((const float4*)pool)[r * 32 + lane];
        float ss = u.x*u.x + u.y*u.y + u.z*u.z + u.w*u.w;
        #pragma unroll
        for (int o = 16; o > 0; o >>= 1) ss += __shfl_xor_sync(0xFFFFFFFFu, ss, o);
        float inv = 1.0f / fmaxf(sqrtf(ss), 1e-12f);
        float f[4] = {u.x * inv, u.y * inv, u.z * inv, u.w * inv};
        uint32_t h[2], l2[2];
        #pragma unroll
        for (int i = 0; i < 2; i++) {
            __nv_bfloat16 h0 = __float2bfloat16(f[2*i]);
            __nv_bfloat16 h1 = __float2bfloat16(f[2*i+1]);
            __nv_bfloat162 hp(h0, h1);
            __nv_bfloat162 lp(__float2bfloat16(f[2*i]   - __bfloat162float(h0)),
                              __float2bfloat16(f[2*i+1] - __bfloat162float(h1)));
            h[i]  = *(uint32_t*)&hp;
            l2[i] = *(uint32_t*)&lp;
        }
        ((uint2*)g_p_hi)[r * 32 + lane] = make_uint2(h[0], h[1]);
        ((uint2*)g_p_lo)[r * 32 + lane] = make_uint2(l2[0], l2[1]);
    }

    // query writes: fp32 + bf16 hi/lo (scattered small stores)
    int qoff = (b * KK + k) * CC + c;
    ((float*)g_q)[qoff] = v;
    __nv_bfloat16 hv = __float2bfloat16(v);
    ((__nv_bfloat16*)g_q_hi)[qoff] = hv;
    ((__nv_bfloat16*)g_q_lo)[qoff] = __float2bfloat16(v - __bfloat162float(hv));
}

// ---------------------------------------------------------------------------
// Kernel 2: tensor-core GEMM via mma.sync bf16 (3-product split) + max.
// grid = (64 pblk, 8 qblk), 256 threads (8 warps). Warp w: qg=w>>1 (16 q rows),
// pg=w&1 (32 p cols = 4 n8 tiles). K staged in 2 chunks of 64.
// Fragment loads are spec-exact LDS.32 per the PTX m16n8k16 lane maps.
// ---------------------------------------------------------------------------
__global__ void __launch_bounds__(256)
gemm_kernel(float* __restrict__ dummy) {
    __shared__ __align__(16) char sm[4 * 64 * SROW];   // 36864 B
    char* qh = sm;
    char* ql = sm + 64 * SROW;
    char* ph = sm + 2 * 64 * SROW;
    char* pl = sm + 3 * 64 * SROW;

    int t = threadIdx.x, l = t & 31, w = t >> 5;
    int qg = w >> 1, pg = w & 1;
    int pblk = blockIdx.x, qblk = blockIdx.y;
    int qbase = qblk * 64, pbase = pblk * 64;

    float d[4][4];
    #pragma unroll
    for (int n = 0; n < 4; n++)
        #pragma unroll
        for (int i = 0; i < 4; i++) d[n][i] = 0.0f;

    for (int kc = 0; kc < 2; kc++) {
        if (kc) __syncthreads();
        // stage 64 rows x 64 bf16 cols for 4 tensors (512 uint4 each)
        #pragma unroll
        for (int i = 0; i < 2; i++) {
            int idx = t + i * 256;           // 0..511
            int r = idx >> 3, c8 = idx & 7;
            int dst = r * SROW + c8 * 16;
            int gq = (qbase + r) * 16 + kc * 8 + c8;
            int gp = (pbase + r) * 16 + kc * 8 + c8;
            *(uint4*)(qh + dst) = g_q_hi[gq];
            *(uint4*)(ql + dst) = g_q_lo[gq];
            *(uint4*)(ph + dst) = g_p_hi[gp];
            *(uint4*)(pl + dst) = g_p_lo[gp];
        }
        __syncthreads();

        #pragma unroll
        for (int kch = 0; kch < 4; kch++) {
            int colb = kch * 32 + (l & 3) * 4;
            // A fragments (hi and lo): rows qg*16 + l/4 (+8), cols colb (+16)
            const char* ar = qh + (qg * 16 + (l >> 2)) * SROW + colb;
            const char* arl = ql + (qg * 16 + (l >> 2)) * SROW + colb;
            uint32_t ah0 = *(const uint32_t*)(ar);
            uint32_t ah1 = *(const uint32_t*)(ar + 8 * SROW);
            uint32_t ah2 = *(const uint32_t*)(ar + 16);
            uint32_t ah3 = *(const uint32_t*)(ar + 8 * SROW + 16);
            uint32_t al0 = *(const uint32_t*)(arl);
            uint32_t al1 = *(const uint32_t*)(arl + 8 * SROW);
            uint32_t al2 = *(const uint32_t*)(arl + 16);
            uint32_t al3 = *(const uint32_t*)(arl + 8 * SROW + 16);
            #pragma unroll
            for (int n = 0; n < 4; n++) {
                const char* brh = ph + (pg * 32 + n * 8 + (l >> 2)) * SROW + colb;
                const char* brl = pl + (pg * 32 + n * 8 + (l >> 2)) * SROW + colb;
                uint32_t bh0 = *(const uint32_t*)(brh);
                uint32_t bh1 = *(const uint32_t*)(brh + 16);
                uint32_t bl0 = *(const uint32_t*)(brl);
                uint32_t bl1 = *(const uint32_t*)(brl + 16);
                MMA_BF16(d[n], ah0, ah1, ah2, ah3, bh0, bh1);   // hi*hi
                MMA_BF16(d[n], ah0, ah1, ah2, ah3, bl0, bl1);   // hi*lo
                MMA_BF16(d[n], al0, al1, al2, al3, bh0, bh1);   // lo*hi
            }
        }
    }

    // epilogue: lane holds rows l/4 (d0,d1) and l/4+8 (d2,d3), cols 2(l%4)+{0,1}
    float m0 = -1e30f, m1 = -1e30f;
    #pragma unroll
    for (int n = 0; n < 4; n++) {
        m0 = fmaxf(m0, fmaxf(d[n][0], d[n][1]));
        m1 = fmaxf(m1, fmaxf(d[n][2], d[n][3]));
    }
    // max over the 4 lanes sharing each row (quad: xor 1, 2)
    m0 = fmaxf(m0, __shfl_xor_sync(0xFFFFFFFFu, m0, 1));
    m0 = fmaxf(m0, __shfl_xor_sync(0xFFFFFFFFu, m0, 2));
    m1 = fmaxf(m1, __shfl_xor_sync(0xFFFFFFFFu, m1, 1));
    m1 = fmaxf(m1, __shfl_xor_sync(0xFFFFFFFFu, m1, 2));
    if ((l & 3) == 0) {
        int q0 = qbase + qg * 16 + (l >> 2);
        g_pmax_val[q0 * 128 + pblk * 2 + pg] = m0;
        g_pmax_val[(q0 + 8) * 128 + pblk * 2 + pg] = m1;
    }
    (void)dummy;
}

// ---------------------------------------------------------------------------
// Kernel 3: finalize — warp per query (hoisted loads), ticket-elected
// deterministic mean. grid = 128 blocks x 128 threads.
// ---------------------------------------------------------------------------
__global__ void __launch_bounds__(128)
finalize_kernel(const float* __restrict__ negs, float* __restrict__ out) {
    __shared__ float loss_sm[4];
    __shared__ int   s_last;
    int t = threadIdx.x, w = t >> 5, lane = t & 31;
    int q = blockIdx.x * 4 + w;
    int b = q >> 6, k = q & 63;

    // hoisted loads: query vec, 4 pmax partials, 7 negative vecs
    float4 qv = g_q[q * 32 + lane];
    float pm0 = g_pmax_val[q * 128 + lane];
    float pm1 = g_pmax_val[q * 128 + 32 + lane];
    float pm2 = g_pmax_val[q * 128 + 64 + lane];
    float pm3 = g_pmax_val[q * 128 + 96 + lane];
    float4 nv[NNEG];
    const float* nbase = negs + ((long)(b * KK + k)) * NNEG * CC;
    #pragma unroll
    for (int n = 0; n < NNEG; n++)
        nv[n] = ((const float4*)(nbase + n * CC))[lane];

    float qss = qv.x*qv.x + qv.y*qv.y + qv.z*qv.z + qv.w*qv.w;
    float v1 = fmaxf(fmaxf(pm0, pm1), fmaxf(pm2, pm3));
    float ss[NNEG], dt[NNEG];
    #pragma unroll
    for (int n = 0; n < NNEG; n++) {
        ss[n] = nv[n].x*nv[n].x + nv[n].y*nv[n].y + nv[n].z*nv[n].z + nv[n].w*nv[n].w;
        dt[n] = nv[n].x*qv.x + nv[n].y*qv.y + nv[n].z*qv.z + nv[n].w*qv.w;
    }
    #pragma unroll
    for (int o = 16; o > 0; o >>= 1) {
        qss += __shfl_xor_sync(0xFFFFFFFFu, qss, o);
        v1 = fmaxf(v1, __shfl_xor_sync(0xFFFFFFFFu, v1, o));
        #pragma unroll
        for (int n = 0; n < NNEG; n++) {
            ss[n] += __shfl_xor_sync(0xFFFFFFFFu, ss[n], o);
            dt[n] += __shfl_xor_sync(0xFFFFFFFFu, dt[n], o);
        }
    }
    if (lane == 0) {
        float invq = 1.0f / fmaxf(sqrtf(qss), 1e-12f);
        float l0 = v1 * invq / TAU;
        float m = l0;
        float ln[NNEG];
        #pragma unroll
        for (int n = 0; n < NNEG; n++) {
            ln[n] = (dt[n] * invq / fmaxf(sqrtf(ss[n]), 1e-12f)) / TAU;
            m = fmaxf(m, ln[n]);
        }
        float sum = expf(l0 - m);
        #pragma unroll
        for (int n = 0; n < NNEG; n++) sum += expf(ln[n] - m);
        loss_sm[w] = m + logf(sum) - l0;
    }
    __syncthreads();

    if (t == 0) {
        g_loss_blk[blockIdx.x] = loss_sm[0] + loss_sm[1] + loss_sm[2] + loss_sm[3];
        __threadfence();
        int tk = atomicAdd(&g_ticket, 1);
        s_last = (tk == 127) ? 1 : 0;
    }
    __syncthreads();

    if (s_last) {
        __shared__ float red[128];
        red[t] = g_loss_blk[t];
        __syncthreads();
        #pragma unroll
        for (int s = 64; s >= 1; s >>= 1) {
            if (t < s) red[t] += red[t + s];
            __syncthreads();
        }
        if (t == 0) out[0] = red[0] / (float)NQ;
    }
}

extern "C" void kernel_launch(void* const* d_in, const int* in_sizes, int n_in,
                              void* d_out, int out_size) {
    const float* query_feat = (const float*)d_in[0];
    const float* pos_pool   = (const float*)d_in[1];
    const float* neg_protos = (const float*)d_in[2];
    const int*   query_idx  = (const int*)d_in[3];
    float* out = (float*)d_out;

    prep_kernel<<<256, 256>>>(query_feat, pos_pool, query_idx);
    dim3 grid(64, 8);
    gemm_kernel<<<grid, 256>>>(out);
    finalize_kernel<<<128, 128>>>(neg_protos, out);
}

// round 13
// speedup vs baseline: 1.3660x; 1.0136x over previous
#include <cuda_runtime.h>
#include <cuda_bf16.h>
#include <math.h>
#include <cstdint>

// Problem constants
#define TAU   0.07f
#define BB    8
#define CC    128
#define HH    512
#define WW    512
#define HWSZ  (HH*WW)
#define KK    64
#define NNEG  7
#define PP    4096
#define NQ    (BB*KK)          // 512
#define SROW  144              // smem row stride in bytes (72 bf16 = 64 + 8 pad)

// Device scratch (allocation-free)
__device__ float4 g_q[NQ * 32];        // RAW gathered queries fp32 [NQ][C]
__device__ uint4  g_q_hi[NQ * 16];     // queries bf16 hi [NQ][C]
__device__ uint4  g_q_lo[NQ * 16];     // queries bf16 lo residual
__device__ uint4  g_p_hi[PP * 16];     // NORMALIZED pool bf16 hi [P][C]
__device__ uint4  g_p_lo[PP * 16];     // normalized pool bf16 lo residual
__device__ float  g_pmax_val[NQ * 128];// per (query, pcol-block) max cos*|q|
__device__ float  g_loss_blk[128];
__device__ int    g_ticket;

#define MMA_BF16(D, A0, A1, A2, A3, B0, B1)                                   \
    asm volatile(                                                             \
        "mma.sync.aligned.m16n8k16.row.col.f32.bf16.bf16.f32 "                \
        "{%0,%1,%2,%3}, {%4,%5,%6,%7}, {%8,%9}, {%0,%1,%2,%3};"               \
        : "+f"(D[0]), "+f"(D[1]), "+f"(D[2]), "+f"(D[3])                      \
        : "r"(A0), "r"(A1), "r"(A2), "r"(A3), "r"(B0), "r"(B1))

#define LDSM_X4(R, ADDR)                                                      \
    asm volatile("ldmatrix.sync.aligned.m8n8.x4.shared.b16 {%0,%1,%2,%3}, [%4];" \
        : "=r"((R)[0]), "=r"((R)[1]), "=r"((R)[2]), "=r"((R)[3]) : "r"(ADDR))

__device__ __forceinline__ uint32_t smem_u32(const void* p) {
    uint32_t a;
    asm("{ .reg .u64 t; cvta.to.shared.u64 t, %1; cvt.u32.u64 %0, t; }"
        : "=r"(a) : "l"(p));
    return a;
}

// ---------------------------------------------------------------------------
// Kernel 1: gather queries (TLB-friendly: warp = one (b,c) page, lanes = k),
// write fp32 + bf16 hi/lo; normalize pool rows, write bf16 hi/lo; reset ticket.
// 256 blocks x 256 threads.
// ---------------------------------------------------------------------------
__global__ void __launch_bounds__(256)
prep_kernel(const float* __restrict__ qf,
            const float* __restrict__ pool,
            const int*   __restrict__ qidx) {
    int t = threadIdx.x, bid = blockIdx.x;
    int w = t >> 5, lane = t & 31;
    if (bid == 0 && t == 0) g_ticket = 0;

    int e = bid * 256 + t;
    int k = e & 63;
    int c = (e >> 6) & 127;
    int b = e >> 13;
    int idx = qidx[b * KK + k];
    float v = qf[(long)(b * CC + c) * HWSZ + idx];

    #pragma unroll
    for (int j = 0; j < 2; j++) {
        int r = bid * 16 + w * 2 + j;
        float4 u = ((const float4*)pool)[r * 32 + lane];
        float ss = u.x*u.x + u.y*u.y + u.z*u.z + u.w*u.w;
        #pragma unroll
        for (int o = 16; o > 0; o >>= 1) ss += __shfl_xor_sync(0xFFFFFFFFu, ss, o);
        float inv = 1.0f / fmaxf(sqrtf(ss), 1e-12f);
        float f[4] = {u.x * inv, u.y * inv, u.z * inv, u.w * inv};
        uint32_t h[2], l2[2];
        #pragma unroll
        for (int i = 0; i < 2; i++) {
            __nv_bfloat16 h0 = __float2bfloat16(f[2*i]);
            __nv_bfloat16 h1 = __float2bfloat16(f[2*i+1]);
            __nv_bfloat162 hp(h0, h1);
            __nv_bfloat162 lp(__float2bfloat16(f[2*i]   - __bfloat162float(h0)),
                              __float2bfloat16(f[2*i+1] - __bfloat162float(h1)));
            h[i]  = *(uint32_t*)&hp;
            l2[i] = *(uint32_t*)&lp;
        }
        ((uint2*)g_p_hi)[r * 32 + lane] = make_uint2(h[0], h[1]);
        ((uint2*)g_p_lo)[r * 32 + lane] = make_uint2(l2[0], l2[1]);
    }

    int qoff = (b * KK + k) * CC + c;
    ((float*)g_q)[qoff] = v;
    __nv_bfloat16 hv = __float2bfloat16(v);
    ((__nv_bfloat16*)g_q_hi)[qoff] = hv;
    ((__nv_bfloat16*)g_q_lo)[qoff] = __float2bfloat16(v - __bfloat162float(hv));
}

// ---------------------------------------------------------------------------
// Kernel 2: tensor-core GEMM (mma.sync bf16, 3-product split) + max.
// grid = (64 pblk, 8 qblk), 256 threads (8 warps). Warp w: qg=w>>1 (16 q),
// pg=w&1 (32 p = 4 n8 tiles). Fragments via ldmatrix.x4 (conflict-free at
// SROW=144). K staged in 2 chunks of 64.
// ---------------------------------------------------------------------------
__global__ void __launch_bounds__(256)
gemm_kernel(float* __restrict__ dummy) {
    __shared__ __align__(16) char sm[4 * 64 * SROW];   // 36864 B
    char* qh = sm;
    char* ql = sm + 64 * SROW;
    char* ph = sm + 2 * 64 * SROW;
    char* pl = sm + 3 * 64 * SROW;

    int t = threadIdx.x, l = t & 31, w = t >> 5;
    int qg = w >> 1, pg = w & 1;
    int pblk = blockIdx.x, qblk = blockIdx.y;
    int qbase = qblk * 64, pbase = pblk * 64;

    // ldmatrix lane-address bases (byte offsets within each tensor tile)
    // A (x4): lanes 0-7 -> rows 0-7 col0 | 8-15 -> rows 8-15 col0
    //         16-23 -> rows 0-7 col+16B | 24-31 -> rows 8-15 col+16B
    uint32_t a_off = (uint32_t)((qg * 16 + (l & 15)) * SROW + ((l >> 4) << 4));
    // B (x4, n-tile pair j): lanes 0-7 rows0-7 col0 | 8-15 rows0-7 col+16 |
    //                        16-23 rows8-15 col0    | 24-31 rows8-15 col+16
    uint32_t b_row = (uint32_t)(pg * 32 + (l & 7) + ((l >> 4) << 3));
    uint32_t b_off0 = (b_row)      * SROW + (((l >> 3) & 1) << 4);
    uint32_t b_off1 = (b_row + 16) * SROW + (((l >> 3) & 1) << 4);

    uint32_t qh_u = smem_u32(qh), ql_u = smem_u32(ql);
    uint32_t ph_u = smem_u32(ph), pl_u = smem_u32(pl);

    float d[4][4];
    #pragma unroll
    for (int n = 0; n < 4; n++)
        #pragma unroll
        for (int i = 0; i < 4; i++) d[n][i] = 0.0f;

    for (int kc = 0; kc < 2; kc++) {
        if (kc) __syncthreads();
        #pragma unroll
        for (int i = 0; i < 2; i++) {
            int idx = t + i * 256;           // 0..511
            int r = idx >> 3, c8 = idx & 7;
            int dst = r * SROW + c8 * 16;
            int gq = (qbase + r) * 16 + kc * 8 + c8;
            int gp = (pbase + r) * 16 + kc * 8 + c8;
            *(uint4*)(qh + dst) = g_q_hi[gq];
            *(uint4*)(ql + dst) = g_q_lo[gq];
            *(uint4*)(ph + dst) = g_p_hi[gp];
            *(uint4*)(pl + dst) = g_p_lo[gp];
        }
        __syncthreads();

        #pragma unroll
        for (int kch = 0; kch < 4; kch++) {
            uint32_t ko = kch * 32;
            uint32_t ah[4], al[4], bh[8], bl[8];
            LDSM_X4(ah,     qh_u + a_off + ko);
            LDSM_X4(al,     ql_u + a_off + ko);
            LDSM_X4(bh,     ph_u + b_off0 + ko);
            LDSM_X4(bh + 4, ph_u + b_off1 + ko);
            LDSM_X4(bl,     pl_u + b_off0 + ko);
            LDSM_X4(bl + 4, pl_u + b_off1 + ko);
            #pragma unroll
            for (int n = 0; n < 4; n++) {
                uint32_t b0 = bh[n * 2], b1 = bh[n * 2 + 1];
                uint32_t c0 = bl[n * 2], c1 = bl[n * 2 + 1];
                MMA_BF16(d[n], ah[0], ah[1], ah[2], ah[3], b0, b1);   // hi*hi
                MMA_BF16(d[n], ah[0], ah[1], ah[2], ah[3], c0, c1);   // hi*lo
                MMA_BF16(d[n], al[0], al[1], al[2], al[3], b0, b1);   // lo*hi
            }
        }
    }

    // epilogue: lane holds rows l/4 (d0,d1) and l/4+8 (d2,d3)
    float m0 = -1e30f, m1 = -1e30f;
    #pragma unroll
    for (int n = 0; n < 4; n++) {
        m0 = fmaxf(m0, fmaxf(d[n][0], d[n][1]));
        m1 = fmaxf(m1, fmaxf(d[n][2], d[n][3]));
    }
    m0 = fmaxf(m0, __shfl_xor_sync(0xFFFFFFFFu, m0, 1));
    m0 = fmaxf(m0, __shfl_xor_sync(0xFFFFFFFFu, m0, 2));
    m1 = fmaxf(m1, __shfl_xor_sync(0xFFFFFFFFu, m1, 1));
    m1 = fmaxf(m1, __shfl_xor_sync(0xFFFFFFFFu, m1, 2));
    if ((l & 3) == 0) {
        int q0 = qbase + qg * 16 + (l >> 2);
        g_pmax_val[q0 * 128 + pblk * 2 + pg] = m0;
        g_pmax_val[(q0 + 8) * 128 + pblk * 2 + pg] = m1;
    }
    (void)dummy;
}

// ---------------------------------------------------------------------------
// Kernel 3: finalize — warp per query (hoisted loads), ticket-elected
// deterministic mean. grid = 128 blocks x 128 threads.
// ---------------------------------------------------------------------------
__global__ void __launch_bounds__(128)
finalize_kernel(const float* __restrict__ negs, float* __restrict__ out) {
    __shared__ float loss_sm[4];
    __shared__ int   s_last;
    int t = threadIdx.x, w = t >> 5, lane = t & 31;
    int q = blockIdx.x * 4 + w;
    int b = q >> 6, k = q & 63;

    float4 qv = g_q[q * 32 + lane];
    float pm0 = g_pmax_val[q * 128 + lane];
    float pm1 = g_pmax_val[q * 128 + 32 + lane];
    float pm2 = g_pmax_val[q * 128 + 64 + lane];
    float pm3 = g_pmax_val[q * 128 + 96 + lane];
    float4 nv[NNEG];
    const float* nbase = negs + ((long)(b * KK + k)) * NNEG * CC;
    #pragma unroll
    for (int n = 0; n < NNEG; n++)
        nv[n] = ((const float4*)(nbase + n * CC))[lane];

    float qss = qv.x*qv.x + qv.y*qv.y + qv.z*qv.z + qv.w*qv.w;
    float v1 = fmaxf(fmaxf(pm0, pm1), fmaxf(pm2, pm3));
    float ss[NNEG], dt[NNEG];
    #pragma unroll
    for (int n = 0; n < NNEG; n++) {
        ss[n] = nv[n].x*nv[n].x + nv[n].y*nv[n].y + nv[n].z*nv[n].z + nv[n].w*nv[n].w;
        dt[n] = nv[n].x*qv.x + nv[n].y*qv.y + nv[n].z*qv.z + nv[n].w*qv.w;
    }
    #pragma unroll
    for (int o = 16; o > 0; o >>= 1) {
        qss += __shfl_xor_sync(0xFFFFFFFFu, qss, o);
        v1 = fmaxf(v1, __shfl_xor_sync(0xFFFFFFFFu, v1, o));
        #pragma unroll
        for (int n = 0; n < NNEG; n++) {
            ss[n] += __shfl_xor_sync(0xFFFFFFFFu, ss[n], o);
            dt[n] += __shfl_xor_sync(0xFFFFFFFFu, dt[n], o);
        }
    }
    if (lane == 0) {
        float invq = 1.0f / fmaxf(sqrtf(qss), 1e-12f);
        float l0 = v1 * invq / TAU;
        float m = l0;
        float ln[NNEG];
        #pragma unroll
        for (int n = 0; n < NNEG; n++) {
            ln[n] = (dt[n] * invq / fmaxf(sqrtf(ss[n]), 1e-12f)) / TAU;
            m = fmaxf(m, ln[n]);
        }
        float sum = expf(l0 - m);
        #pragma unroll
        for (int n = 0; n < NNEG; n++) sum += expf(ln[n] - m);
        loss_sm[w] = m + logf(sum) - l0;
    }
    __syncthreads();

    if (t == 0) {
        g_loss_blk[blockIdx.x] = loss_sm[0] + loss_sm[1] + loss_sm[2] + loss_sm[3];
        __threadfence();
        int tk = atomicAdd(&g_ticket, 1);
        s_last = (tk == 127) ? 1 : 0;
    }
    __syncthreads();

    if (s_last) {
        __shared__ float red[128];
        red[t] = g_loss_blk[t];
        __syncthreads();
        #pragma unroll
        for (int s = 64; s >= 1; s >>= 1) {
            if (t < s) red[t] += red[t + s];
            __syncthreads();
        }
        if (t == 0) out[0] = red[0] / (float)NQ;
    }
}

extern "C" void kernel_launch(void* const* d_in, const int* in_sizes, int n_in,
                              void* d_out, int out_size) {
    const float* query_feat = (const float*)d_in[0];
    const float* pos_pool   = (const float*)d_in[1];
    const float* neg_protos = (const float*)d_in[2];
    const int*   query_idx  = (const int*)d_in[3];
    float* out = (float*)d_out;

    prep_kernel<<<256, 256>>>(query_feat, pos_pool, query_idx);
    dim3 grid(64, 8);
    gemm_kernel<<<grid, 256>>>(out);
    finalize_kernel<<<128, 128>>>(neg_protos, out);
}

// round 14
// speedup vs baseline: 1.5244x; 1.1160x over previous
#include <cuda_runtime.h>
#include <cuda_bf16.h>
#include <math.h>
#include <cstdint>

// Problem constants
#define TAU   0.07f
#define BB    8
#define CC    128
#define HH    512
#define WW    512
#define HWSZ  (HH*WW)
#define KK    64
#define NNEG  7
#define PP    4096
#define NQ    (BB*KK)          // 512
#define SROW  144              // smem row stride in bytes (72 bf16)
#define GSMEM (4 * 128 * SROW) // 73728 B dynamic smem for gemm

// Device scratch (allocation-free)
__device__ float4 g_q[NQ * 32];        // RAW gathered queries fp32 [NQ][C]
__device__ uint4  g_q_hi[NQ * 16];     // queries bf16 hi [NQ][C]
__device__ uint4  g_q_lo[NQ * 16];     // queries bf16 lo residual
__device__ uint4  g_p_hi[PP * 16];     // NORMALIZED pool bf16 hi [P][C]
__device__ uint4  g_p_lo[PP * 16];     // normalized pool bf16 lo residual
__device__ float  g_pmax_val[NQ * 32]; // per (query, pcol-block) max cos*|q|
__device__ float  g_loss_blk[128];
__device__ int    g_ticket;

#define MMA_BF16(D, A0, A1, A2, A3, B0, B1)                                   \
    asm volatile(                                                             \
        "mma.sync.aligned.m16n8k16.row.col.f32.bf16.bf16.f32 "                \
        "{%0,%1,%2,%3}, {%4,%5,%6,%7}, {%8,%9}, {%0,%1,%2,%3};"               \
        : "+f"(D[0]), "+f"(D[1]), "+f"(D[2]), "+f"(D[3])                      \
        : "r"(A0), "r"(A1), "r"(A2), "r"(A3), "r"(B0), "r"(B1))

#define LDSM_X4(R, ADDR)                                                      \
    asm volatile("ldmatrix.sync.aligned.m8n8.x4.shared.b16 {%0,%1,%2,%3}, [%4];" \
        : "=r"((R)[0]), "=r"((R)[1]), "=r"((R)[2]), "=r"((R)[3]) : "r"(ADDR))

__device__ __forceinline__ uint32_t smem_u32(const void* p) {
    uint32_t a;
    asm("{ .reg .u64 t; cvta.to.shared.u64 t, %1; cvt.u32.u64 %0, t; }"
        : "=r"(a) : "l"(p));
    return a;
}

// ---------------------------------------------------------------------------
// Kernel 1: gather queries (TLB-friendly) + pool normalize/convert + reset.
// 256 blocks x 256 threads. (unchanged, proven)
// ---------------------------------------------------------------------------
__global__ void __launch_bounds__(256)
prep_kernel(const float* __restrict__ qf,
            const float* __restrict__ pool,
            const int*   __restrict__ qidx) {
    int t = threadIdx.x, bid = blockIdx.x;
    int w = t >> 5, lane = t & 31;
    if (bid == 0 && t == 0) g_ticket = 0;

    int e = bid * 256 + t;
    int k = e & 63;
    int c = (e >> 6) & 127;
    int b = e >> 13;
    int idx = qidx[b * KK + k];
    float v = qf[(long)(b * CC + c) * HWSZ + idx];

    #pragma unroll
    for (int j = 0; j < 2; j++) {
        int r = bid * 16 + w * 2 + j;
        float4 u = ((const float4*)pool)[r * 32 + lane];
        float ss = u.x*u.x + u.y*u.y + u.z*u.z + u.w*u.w;
        #pragma unroll
        for (int o = 16; o > 0; o >>= 1) ss += __shfl_xor_sync(0xFFFFFFFFu, ss, o);
        float inv = 1.0f / fmaxf(sqrtf(ss), 1e-12f);
        float f[4] = {u.x * inv, u.y * inv, u.z * inv, u.w * inv};
        uint32_t h[2], l2[2];
        #pragma unroll
        for (int i = 0; i < 2; i++) {
            __nv_bfloat16 h0 = __float2bfloat16(f[2*i]);
            __nv_bfloat16 h1 = __float2bfloat16(f[2*i+1]);
            __nv_bfloat162 hp(h0, h1);
            __nv_bfloat162 lp(__float2bfloat16(f[2*i]   - __bfloat162float(h0)),
                              __float2bfloat16(f[2*i+1] - __bfloat162float(h1)));
            h[i]  = *(uint32_t*)&hp;
            l2[i] = *(uint32_t*)&lp;
        }
        ((uint2*)g_p_hi)[r * 32 + lane] = make_uint2(h[0], h[1]);
        ((uint2*)g_p_lo)[r * 32 + lane] = make_uint2(l2[0], l2[1]);
    }

    int qoff = (b * KK + k) * CC + c;
    ((float*)g_q)[qoff] = v;
    __nv_bfloat16 hv = __float2bfloat16(v);
    ((__nv_bfloat16*)g_q_hi)[qoff] = hv;
    ((__nv_bfloat16*)g_q_lo)[qoff] = __float2bfloat16(v - __bfloat162float(hv));
}

// ---------------------------------------------------------------------------
// Kernel 2: tensor GEMM, tile 128q x 128p. grid = (32 pblk, 4 qblk), 256 thr.
// Warp w = 16 q rows; loops 4 p-chunks of 32 cols. 3-product bf16 split.
// K staged in 2 chunks of 64 (kc). Dynamic smem 72 KB.
// ---------------------------------------------------------------------------
__global__ void __launch_bounds__(256)
gemm_kernel() {
    extern __shared__ __align__(16) char sm[];
    char* qh = sm;
    char* ql = sm + 128 * SROW;
    char* ph = sm + 2 * 128 * SROW;
    char* pl = sm + 3 * 128 * SROW;

    int t = threadIdx.x, l = t & 31, w = t >> 5;
    int pblk = blockIdx.x, qblk = blockIdx.y;
    int qbase = qblk * 128, pbase = pblk * 128;

    // ldmatrix lane-address bases (R13-proven maps)
    uint32_t a_off = (uint32_t)((w * 16 + (l & 15)) * SROW + ((l >> 4) << 4));
    uint32_t b_row = (uint32_t)((l & 7) + ((l >> 4) << 3));
    uint32_t b_off0 = (b_row)      * SROW + (((l >> 3) & 1) << 4);
    uint32_t b_off1 = (b_row + 16) * SROW + (((l >> 3) & 1) << 4);

    uint32_t qh_u = smem_u32(qh), ql_u = smem_u32(ql);
    uint32_t ph_u = smem_u32(ph), pl_u = smem_u32(pl);

    float d[16][4];
    #pragma unroll
    for (int n = 0; n < 16; n++)
        #pragma unroll
        for (int i = 0; i < 4; i++) d[n][i] = 0.0f;

    for (int kc = 0; kc < 2; kc++) {
        if (kc) __syncthreads();
        // stage 128 rows x 64 bf16 cols for 4 tensors (1024 uint4 each)
        #pragma unroll
        for (int i = 0; i < 4; i++) {
            int idx = t + i * 256;           // 0..1023
            int r = idx >> 3, c8 = idx & 7;
            int dst = r * SROW + c8 * 16;
            int gq = (qbase + r) * 16 + kc * 8 + c8;
            int gp = (pbase + r) * 16 + kc * 8 + c8;
            *(uint4*)(qh + dst) = g_q_hi[gq];
            *(uint4*)(ql + dst) = g_q_lo[gq];
            *(uint4*)(ph + dst) = g_p_hi[gp];
            *(uint4*)(pl + dst) = g_p_lo[gp];
        }
        __syncthreads();

        #pragma unroll
        for (int kch = 0; kch < 4; kch++) {
            uint32_t ko = kch * 32;
            uint32_t ah[4], al[4];
            LDSM_X4(ah, qh_u + a_off + ko);
            LDSM_X4(al, ql_u + a_off + ko);
            #pragma unroll
            for (int pc = 0; pc < 4; pc++) {
                uint32_t po = pc * 32 * SROW;
                uint32_t bh[8], bl[8];
                LDSM_X4(bh,     ph_u + po + b_off0 + ko);
                LDSM_X4(bh + 4, ph_u + po + b_off1 + ko);
                LDSM_X4(bl,     pl_u + po + b_off0 + ko);
                LDSM_X4(bl + 4, pl_u + po + b_off1 + ko);
                #pragma unroll
                for (int n = 0; n < 4; n++) {
                    float* dd = d[pc * 4 + n];
                    uint32_t b0 = bh[n * 2], b1 = bh[n * 2 + 1];
                    uint32_t c0 = bl[n * 2], c1 = bl[n * 2 + 1];
                    MMA_BF16(dd, ah[0], ah[1], ah[2], ah[3], b0, b1);   // hi*hi
                    MMA_BF16(dd, ah[0], ah[1], ah[2], ah[3], c0, c1);   // hi*lo
                    MMA_BF16(dd, al[0], al[1], al[2], al[3], b0, b1);   // lo*hi
                }
            }
        }
    }

    // epilogue: lane holds rows l/4 and l/4+8 of this warp's 16 q rows
    float m0 = -1e30f, m1 = -1e30f;
    #pragma unroll
    for (int n = 0; n < 16; n++) {
        m0 = fmaxf(m0, fmaxf(d[n][0], d[n][1]));
        m1 = fmaxf(m1, fmaxf(d[n][2], d[n][3]));
    }
    m0 = fmaxf(m0, __shfl_xor_sync(0xFFFFFFFFu, m0, 1));
    m0 = fmaxf(m0, __shfl_xor_sync(0xFFFFFFFFu, m0, 2));
    m1 = fmaxf(m1, __shfl_xor_sync(0xFFFFFFFFu, m1, 1));
    m1 = fmaxf(m1, __shfl_xor_sync(0xFFFFFFFFu, m1, 2));
    if ((l & 3) == 0) {
        int q0 = qbase + w * 16 + (l >> 2);
        g_pmax_val[q0 * 32 + pblk] = m0;
        g_pmax_val[(q0 + 8) * 32 + pblk] = m1;
    }
}

// ---------------------------------------------------------------------------
// Kernel 3: finalize — warp per query (hoisted loads), ticket-elected
// deterministic mean. grid = 128 blocks x 128 threads.
// ---------------------------------------------------------------------------
__global__ void __launch_bounds__(128)
finalize_kernel(const float* __restrict__ negs, float* __restrict__ out) {
    __shared__ float loss_sm[4];
    __shared__ int   s_last;
    int t = threadIdx.x, w = t >> 5, lane = t & 31;
    int q = blockIdx.x * 4 + w;
    int b = q >> 6, k = q & 63;

    float4 qv = g_q[q * 32 + lane];
    float v1 = g_pmax_val[q * 32 + lane];     // 32 partials, one per lane
    float4 nv[NNEG];
    const float* nbase = negs + ((long)(b * KK + k)) * NNEG * CC;
    #pragma unroll
    for (int n = 0; n < NNEG; n++)
        nv[n] = ((const float4*)(nbase + n * CC))[lane];

    float qss = qv.x*qv.x + qv.y*qv.y + qv.z*qv.z + qv.w*qv.w;
    float ss[NNEG], dt[NNEG];
    #pragma unroll
    for (int n = 0; n < NNEG; n++) {
        ss[n] = nv[n].x*nv[n].x + nv[n].y*nv[n].y + nv[n].z*nv[n].z + nv[n].w*nv[n].w;
        dt[n] = nv[n].x*qv.x + nv[n].y*qv.y + nv[n].z*qv.z + nv[n].w*qv.w;
    }
    #pragma unroll
    for (int o = 16; o > 0; o >>= 1) {
        qss += __shfl_xor_sync(0xFFFFFFFFu, qss, o);
        v1 = fmaxf(v1, __shfl_xor_sync(0xFFFFFFFFu, v1, o));
        #pragma unroll
        for (int n = 0; n < NNEG; n++) {
            ss[n] += __shfl_xor_sync(0xFFFFFFFFu, ss[n], o);
            dt[n] += __shfl_xor_sync(0xFFFFFFFFu, dt[n], o);
        }
    }
    if (lane == 0) {
        float invq = 1.0f / fmaxf(sqrtf(qss), 1e-12f);
        float l0 = v1 * invq / TAU;
        float m = l0;
        float ln[NNEG];
        #pragma unroll
        for (int n = 0; n < NNEG; n++) {
            ln[n] = (dt[n] * invq / fmaxf(sqrtf(ss[n]), 1e-12f)) / TAU;
            m = fmaxf(m, ln[n]);
        }
        float sum = expf(l0 - m);
        #pragma unroll
        for (int n = 0; n < NNEG; n++) sum += expf(ln[n] - m);
        loss_sm[w] = m + logf(sum) - l0;
    }
    __syncthreads();

    if (t == 0) {
        g_loss_blk[blockIdx.x] = loss_sm[0] + loss_sm[1] + loss_sm[2] + loss_sm[3];
        __threadfence();
        int tk = atomicAdd(&g_ticket, 1);
        s_last = (tk == 127) ? 1 : 0;
    }
    __syncthreads();

    if (s_last) {
        __shared__ float red[128];
        red[t] = g_loss_blk[t];
        __syncthreads();
        #pragma unroll
        for (int s = 64; s >= 1; s >>= 1) {
            if (t < s) red[t] += red[t + s];
            __syncthreads();
        }
        if (t == 0) out[0] = red[0] / (float)NQ;
    }
}

extern "C" void kernel_launch(void* const* d_in, const int* in_sizes, int n_in,
                              void* d_out, int out_size) {
    const float* query_feat = (const float*)d_in[0];
    const float* pos_pool   = (const float*)d_in[1];
    const float* neg_protos = (const float*)d_in[2];
    const int*   query_idx  = (const int*)d_in[3];
    float* out = (float*)d_out;

    static int smem_set = 0;
    if (!smem_set) {
        cudaFuncSetAttribute(gemm_kernel,
                             cudaFuncAttributeMaxDynamicSharedMemorySize, GSMEM);
        smem_set = 1;
    }

    prep_kernel<<<256, 256>>>(query_feat, pos_pool, query_idx);
    dim3 grid(32, 4);
    gemm_kernel<<<grid, 256, GSMEM>>>();
    finalize_kernel<<<128, 128>>>(neg_protos, out);
}